// round 13
// baseline (speedup 1.0000x reference)
#include <cuda_runtime.h>
#include <cuda_bf16.h>
#include <cstdint>

// MaxUnpooling2D scatter-add.
//   updates: f32 [8,128,128,256] = 33,554,432 elems (134 MB)
//   mask:    i32 same shape, values in [0, 2^24)
//   out:     f32 [8,256,256,256] = 134,217,728 elems (536 MB)
//   flat index = mask[i] + batch * 2^22  (batch offset uses INPUT size)
// Touched range: [0, 46,137,344) words; tail never hit by atomics.
//
// R12: stream-level overlap is FIFO-serialized (R11 post-mortem: the side
// zero's 68us appeared verbatim in the total). Overlap must be block-granular
// inside ONE kernel, with roles INTERLEAVED by blockIdx (R6's epilogue
// ordering and R8's in-warp fusion both tested something else):
//   zero_p0 (hazard, serial, 14us)
//   fused0: even bids scatter pass0 [0,PART), odd bids zero 424 f4 each
//           covering [PART, TOUCHED) + first tail chunk   (13,893,632 f4)
//   fused1: even bids scatter pass1 [PART,TOUCHED), odd bids zero the
//           remaining tail                                 (13,893,632 f4)
// Zero DRAM traffic is balanced across both fused kernels.

static constexpr int N_UPD   = 33554432;    // update elems (8 * 2^22)
static constexpr int N_OUT   = 134217728;   // output elems (8 * 2^24)
static constexpr int TOUCHED = 46137344;    // 2^24 + 7*2^22
static constexpr int PART    = TOUCHED / 2; // 23,068,672 words
static constexpr int BATCH_SHIFT = 22;

static constexpr int SCATTER_BLOCKS = (N_UPD / 4) / 256;   // 32768
static constexpr int FUSED_GRID     = SCATTER_BLOCKS * 2;  // 65536
static constexpr int ZERO_PER_BLOCK = 424;                 // f4 per zero block
// fused0 zeroes f4 [PART/4, PART/4 + 32768*424); check:
//   PART/4 = 5,767,168 ; 32768*424 = 13,893,632
//   5,767,168 + 13,893,632 = 19,660,800  (covers [PART,TOUCHED)=5.77M f4 + tail chunk)
// fused1 zeroes f4 [19,660,800, 19,660,800 + 13,893,632) = [.., 33,554,432) = N_OUT/4. ✓
static constexpr int ZBASE0 = PART / 4;          // 5,767,168
static constexpr int ZBASE1 = 19660800;

__global__ void __launch_bounds__(256) zero_range_kernel(float4* __restrict__ out) {
    int i = blockIdx.x * 256 + threadIdx.x;
    out[i] = make_float4(0.f, 0.f, 0.f, 0.f);
}

// Interleaved-role fused kernel: even blocks scatter (targets in [lo,hi)),
// odd blocks zero ZERO_PER_BLOCK float4 at zbase4.
__global__ void __launch_bounds__(256) fused_pass_kernel(
    const float4* __restrict__ upd4,
    const int4*  __restrict__ mask4,
    float* __restrict__ out,
    int lo, int hi, int zbase4)
{
    int bid = blockIdx.x;
    int t   = threadIdx.x;
    int half = bid >> 1;

    if ((bid & 1) == 0) {
        // Scatter role.
        int i = half * 256 + t;                    // float4 index
        int4   m = __ldcs(mask4 + i);
        float4 u = __ldcs(upd4 + i);
        // elem index = 4*i -> batch = i >> 20; base = batch << 22
        int base = (i >> (BATCH_SHIFT - 2)) << BATCH_SHIFT;
        int ix = base + m.x, iy = base + m.y, iz = base + m.z, iw = base + m.w;
        if (ix >= lo && ix < hi) atomicAdd(out + ix, u.x);
        if (iy >= lo && iy < hi) atomicAdd(out + iy, u.y);
        if (iz >= lo && iz < hi) atomicAdd(out + iz, u.z);
        if (iw >= lo && iw < hi) atomicAdd(out + iw, u.w);
    } else {
        // Zero role: 424 float4.
        const float4 z4 = make_float4(0.f, 0.f, 0.f, 0.f);
        float4* dst = (float4*)out + zbase4 + half * ZERO_PER_BLOCK;
        dst[t] = z4;
        if (t < ZERO_PER_BLOCK - 256) dst[t + 256] = z4;
    }
}

extern "C" void kernel_launch(void* const* d_in, const int* in_sizes, int n_in,
                              void* d_out, int out_size) {
    const float* updates = (const float*)d_in[0];
    const int*   mask    = (const int*)d_in[1];
    float* out = (float*)d_out;

    // 1. Zero partition 0 [0, PART) — must precede pass-0 atomics.
    zero_range_kernel<<<(PART / 4) / 256, 256>>>((float4*)out);

    // 2. fused0: scatter pass0 + zero [PART, ...) incl. first tail chunk.
    fused_pass_kernel<<<FUSED_GRID, 256>>>(
        (const float4*)updates, (const int4*)mask, out, 0, PART, ZBASE0);

    // 3. fused1: scatter pass1 + zero remaining tail.
    fused_pass_kernel<<<FUSED_GRID, 256>>>(
        (const float4*)updates, (const int4*)mask, out, PART, TOUCHED, ZBASE1);
}

// round 14
// speedup vs baseline: 1.2001x; 1.2001x over previous
#include <cuda_runtime.h>
#include <cuda_bf16.h>
#include <cstdint>

// MaxUnpooling2D scatter-add.
//   updates: f32 [8,128,128,256] = 33,554,432 elems (134 MB)
//   mask:    i32 same shape, values in [0, 2^24)
//   out:     f32 [8,256,256,256] = 134,217,728 elems (536 MB)
//   flat index = mask[i] + batch * 2^22  (batch b targets [b*2^22, b*2^22+2^24))
// Touched range: [0, 46,137,344) words; tail never hit.
//
// R13 model (4 failed overlap attempts): zero and scatter share saturated LTS
// -> time is additive. Per pass: reads + atomics, atomics at REDG floor.
// Lever: batch-range pruning. Boundary X = 5*2^22:
//   pass0 targets [0, X):  only batches 0-4 can contribute (b5 min = X)
//                          -> read elems [0, 20,971,520) only
//   pass1 targets [X, ..): only batches 2-7 can contribute (b1 max = X-1)
//                          -> read elems [8,388,608, 33,554,432) only
// Reads drop 536 -> 368 MB. Partitions 84 MB / 100.7 MB, both L2-resident.

static constexpr int N_UPD   = 33554432;     // update elems (8 * 2^22)
static constexpr int N_OUT   = 134217728;    // output elems (8 * 2^24)
static constexpr int TOUCHED = 46137344;     // 2^24 + 7*2^22
static constexpr int PART_X  = 20971520;     // 5 * 2^22
static constexpr int BATCH_SHIFT = 22;

// Pass 0: elems [0, 20,971,520)            -> 5,242,880 f4 -> 20480 blocks
// Pass 1: elems [8,388,608, 33,554,432)    -> 6,291,456 f4 -> 24576 blocks
static constexpr int P0_F4      = PART_X / 4;             // 5,242,880
static constexpr int P1_F4_OFF  = 8388608 / 4;            // 2,097,152
static constexpr int P1_F4      = (N_UPD - 8388608) / 4;  // 6,291,456

__global__ void __launch_bounds__(256) zero_range_kernel(float4* __restrict__ out) {
    int i = blockIdx.x * 256 + threadIdx.x;
    out[i] = make_float4(0.f, 0.f, 0.f, 0.f);
}

// Scatter pass 0: reads f4 [0, P0_F4), applies atomics with target < PART_X.
__global__ void __launch_bounds__(256) scatter_pass0_kernel(
    const float4* __restrict__ upd4,
    const int4*  __restrict__ mask4,
    float* __restrict__ out)
{
    int i = blockIdx.x * 256 + threadIdx.x;        // f4 index, batches 0-4
    int4   m = __ldcs(mask4 + i);
    float4 u = __ldcs(upd4 + i);
    int base = (i >> (BATCH_SHIFT - 2)) << BATCH_SHIFT;   // batch * 2^22
    int ix = base + m.x, iy = base + m.y, iz = base + m.z, iw = base + m.w;
    if (ix < PART_X) atomicAdd(out + ix, u.x);
    if (iy < PART_X) atomicAdd(out + iy, u.y);
    if (iz < PART_X) atomicAdd(out + iz, u.z);
    if (iw < PART_X) atomicAdd(out + iw, u.w);
}

// Scatter pass 1: reads f4 [P1_F4_OFF, P1_F4_OFF+P1_F4) (batches 2-7),
// applies atomics with target >= PART_X (all targets < TOUCHED by construction).
__global__ void __launch_bounds__(256) scatter_pass1_kernel(
    const float4* __restrict__ upd4,
    const int4*  __restrict__ mask4,
    float* __restrict__ out)
{
    int i = P1_F4_OFF + blockIdx.x * 256 + threadIdx.x;   // f4 index
    int4   m = __ldcs(mask4 + i);
    float4 u = __ldcs(upd4 + i);
    int base = (i >> (BATCH_SHIFT - 2)) << BATCH_SHIFT;
    int ix = base + m.x, iy = base + m.y, iz = base + m.z, iw = base + m.w;
    if (ix >= PART_X) atomicAdd(out + ix, u.x);
    if (iy >= PART_X) atomicAdd(out + iy, u.y);
    if (iz >= PART_X) atomicAdd(out + iz, u.z);
    if (iw >= PART_X) atomicAdd(out + iw, u.w);
}

extern "C" void kernel_launch(void* const* d_in, const int* in_sizes, int n_in,
                              void* d_out, int out_size) {
    const float* updates = (const float*)d_in[0];
    const int*   mask    = (const int*)d_in[1];
    float* out = (float*)d_out;

    // zero p0 [0, PART_X): 20480 blocks
    zero_range_kernel<<<(PART_X / 4) / 256, 256>>>((float4*)out);
    // pass 0
    scatter_pass0_kernel<<<P0_F4 / 256, 256>>>(
        (const float4*)updates, (const int4*)mask, out);
    // zero p1 [PART_X, TOUCHED): 24576 blocks
    zero_range_kernel<<<((TOUCHED - PART_X) / 4) / 256, 256>>>(
        (float4*)(out + PART_X));
    // pass 1
    scatter_pass1_kernel<<<P1_F4 / 256, 256>>>(
        (const float4*)updates, (const int4*)mask, out);
    // zero tail [TOUCHED, N_OUT): 86016 blocks
    zero_range_kernel<<<((N_OUT - TOUCHED) / 4) / 256, 256>>>(
        (float4*)(out + TOUCHED));
}